// round 3
// baseline (speedup 1.0000x reference)
#include <cuda_runtime.h>
#include <cuda_bf16.h>
#include <cstdint>

// Problem constants
#define B 32
#define P 196
#define D 512
#define H 8
#define U 4
#define C 500

#define D4 128            // D / 4 (float4)
#define TOK_K 11          // known prompt tokens: pre, dom, sem(8), suf
#define TOK_U 7           // unknown prompt tokens: pre, dom, usem(4), suf

// Output slice offsets (floats), tuple order: known_prompts, unknown_prompts, semantic_tokens
#define N_KNOWN   (16000LL * TOK_K * D)        // 90,112,000
#define OUT_UNK   (N_KNOWN)
#define N_UNK     ((long long)B * TOK_U * D)   // 114,688
#define OUT_SEM   (OUT_UNK + N_UNK)            // 90,226,688

// Scratch (device globals — no allocations allowed)
__device__ float g_scores[B * P * H];          // [b][p][h]
// g_mid[b] = [dom (512) | psem h=0..7 (8*512)] = 4608 floats = 1152 float4.
// Exactly the middle 9 tokens of a known prompt row, contiguous.
__device__ float g_mid[B * 9 * D];

#define MID_F4 (9 * D4)   // 1152

// ---------------------------------------------------------------------------
// K1: scores[b][p][h] = dot(patch[b][p], query[h]); grid = B*P, block = 256
// ---------------------------------------------------------------------------
__global__ void k_scores(const float4* __restrict__ patch,
                         const float4* __restrict__ query) {
    int bp = blockIdx.x;                  // b*P + p
    int w = threadIdx.x >> 5, lane = threadIdx.x & 31;   // warp == head
    const float4* row = patch + (size_t)bp * D4;
    const float4* q = query + (size_t)w * D4;
    float acc = 0.f;
    #pragma unroll
    for (int k = 0; k < 4; k++) {
        float4 r = row[lane + 32 * k];
        float4 qq = q[lane + 32 * k];
        acc = fmaf(r.x, qq.x, acc);
        acc = fmaf(r.y, qq.y, acc);
        acc = fmaf(r.z, qq.z, acc);
        acc = fmaf(r.w, qq.w, acc);
    }
    #pragma unroll
    for (int o = 16; o; o >>= 1) acc += __shfl_xor_sync(0xffffffffu, acc, o);
    if (lane == 0) g_scores[(size_t)bp * H + w] = acc;
}

// ---------------------------------------------------------------------------
// K2: softmax over p (per b,h) then semantic_tokens[b][h][d]
// grid = (B, 4) d-chunks of 128; block = 128. Softmax recomputed per block.
// ---------------------------------------------------------------------------
__global__ void k_tokens(const float* __restrict__ patch,
                         float* __restrict__ out_sem) {
    __shared__ float sw[P][H + 1];
    int b = blockIdx.x, dc = blockIdx.y;
    int tid = threadIdx.x;
    for (int i = tid; i < P * H; i += 128) {
        int p = i >> 3, h = i & 7;
        sw[p][h] = g_scores[(size_t)b * P * H + i];
    }
    __syncthreads();

    int w = tid >> 5, lane = tid & 31;
    for (int h = w; h < H; h += 4) {
        float mx = -3.4e38f;
        for (int p = lane; p < P; p += 32) mx = fmaxf(mx, sw[p][h]);
        #pragma unroll
        for (int o = 16; o; o >>= 1) mx = fmaxf(mx, __shfl_xor_sync(0xffffffffu, mx, o));
        float sum = 0.f;
        for (int p = lane; p < P; p += 32) {
            float e = expf(sw[p][h] - mx);
            sw[p][h] = e;
            sum += e;
        }
        #pragma unroll
        for (int o = 16; o; o >>= 1) sum += __shfl_xor_sync(0xffffffffu, sum, o);
        float inv = 1.f / sum;
        for (int p = lane; p < P; p += 32) sw[p][h] *= inv;
    }
    __syncthreads();

    int d = dc * 128 + tid;
    float acc[H];
    #pragma unroll
    for (int h = 0; h < H; h++) acc[h] = 0.f;
    const float* pb = patch + (size_t)b * P * D + d;
    #pragma unroll 4
    for (int p = 0; p < P; p++) {
        float x = pb[(size_t)p * D];
        #pragma unroll
        for (int h = 0; h < H; h++) acc[h] = fmaf(sw[p][h], x, acc[h]);
    }
    #pragma unroll
    for (int h = 0; h < H; h++)
        out_sem[((size_t)b * H + h) * D + d] = acc[h];
}

// ---------------------------------------------------------------------------
// K3: projected_domain -> g_mid[b][0:512]; grid = B, block = 512
// ---------------------------------------------------------------------------
__global__ void k_dom(const float* __restrict__ G,
                      const float* __restrict__ W,
                      const float* __restrict__ bias) {
    __shared__ float gs[D];
    int b = blockIdx.x, tid = threadIdx.x;
    gs[tid] = G[(size_t)b * D + tid];
    __syncthreads();
    int w = tid >> 5, lane = tid & 31;
    for (int g = 0; g < 8; g++) {
        int e = w * 32 + g * 4;
        float a0 = 0.f, a1 = 0.f, a2 = 0.f, a3 = 0.f;
        const float* w0 = W + (size_t)(e + 0) * D;
        const float* w1 = W + (size_t)(e + 1) * D;
        const float* w2 = W + (size_t)(e + 2) * D;
        const float* w3 = W + (size_t)(e + 3) * D;
        #pragma unroll 4
        for (int d = lane; d < D; d += 32) {
            float x = gs[d];
            a0 = fmaf(w0[d], x, a0);
            a1 = fmaf(w1[d], x, a1);
            a2 = fmaf(w2[d], x, a2);
            a3 = fmaf(w3[d], x, a3);
        }
        #pragma unroll
        for (int o = 16; o; o >>= 1) {
            a0 += __shfl_xor_sync(0xffffffffu, a0, o);
            a1 += __shfl_xor_sync(0xffffffffu, a1, o);
            a2 += __shfl_xor_sync(0xffffffffu, a2, o);
            a3 += __shfl_xor_sync(0xffffffffu, a3, o);
        }
        if (lane == 0) {
            g_mid[(size_t)b * (9 * D) + e + 0] = a0 + bias[e + 0];
            g_mid[(size_t)b * (9 * D) + e + 1] = a1 + bias[e + 1];
            g_mid[(size_t)b * (9 * D) + e + 2] = a2 + bias[e + 2];
            g_mid[(size_t)b * (9 * D) + e + 3] = a3 + bias[e + 3];
        }
    }
}

// ---------------------------------------------------------------------------
// K4: projected_sem -> g_mid[b][(1+h)*512 + e].  lane = b outer-product GEMM:
// no shuffles, accumulators in registers. Each warp owns 2 e-columns.
// grid = (32 e-tiles of 16, H), block = 256 (8 warps x 2 e).
// S (out_sem) is transposed per 32-d chunk through a small smem tile;
// W rows are read exactly once chip-wide as uniform float4 loads.
// ---------------------------------------------------------------------------
__global__ void k_sem(const float* __restrict__ S,
                      const float4* __restrict__ W4,   // (H,E,D) as float4
                      const float* __restrict__ bias) {
    __shared__ float st[32][33];          // d-chunk x b, padded
    int h = blockIdx.y;
    int tid = threadIdx.x, w = tid >> 5, lane = tid & 31;
    int e0 = blockIdx.x * 16 + w * 2;     // this warp's 2 e's

    const float4* wr0 = W4 + ((size_t)h * D + (e0 + 0)) * D4;
    const float4* wr1 = W4 + ((size_t)h * D + (e0 + 1)) * D4;

    float acc0 = 0.f, acc1 = 0.f;

    for (int ch = 0; ch < 16; ch++) {
        int d0 = ch * 32;
        // cooperative transpose: 1024 elems, 4 per thread
        __syncthreads();                  // prior chunk fully consumed
        #pragma unroll
        for (int k = 0; k < 4; k++) {
            int i = tid + k * 256;        // i = b*32 + dd
            int b = i >> 5, dd = i & 31;
            st[dd][b] = S[((size_t)b * H + h) * D + d0 + dd];
        }
        __syncthreads();

        float s[32];
        #pragma unroll
        for (int j = 0; j < 32; j++) s[j] = st[j][lane];

        #pragma unroll
        for (int q = 0; q < 8; q++) {
            float4 v0 = __ldg(&wr0[(d0 >> 2) + q]);
            float4 v1 = __ldg(&wr1[(d0 >> 2) + q]);
            acc0 = fmaf(v0.x, s[4 * q + 0], acc0);
            acc0 = fmaf(v0.y, s[4 * q + 1], acc0);
            acc0 = fmaf(v0.z, s[4 * q + 2], acc0);
            acc0 = fmaf(v0.w, s[4 * q + 3], acc0);
            acc1 = fmaf(v1.x, s[4 * q + 0], acc1);
            acc1 = fmaf(v1.y, s[4 * q + 1], acc1);
            acc1 = fmaf(v1.z, s[4 * q + 2], acc1);
            acc1 = fmaf(v1.w, s[4 * q + 3], acc1);
        }
    }

    float b0 = __ldg(&bias[h * D + e0 + 0]);
    float b1 = __ldg(&bias[h * D + e0 + 1]);
    // lane = b: scatter two floats per lane into g_mid
    size_t base = (size_t)lane * (9 * D) + (size_t)(1 + h) * D;
    g_mid[base + e0 + 0] = acc0 + b0;
    g_mid[base + e0 + 1] = acc1 + b1;
}

// ---------------------------------------------------------------------------
// K5: prompt fill. grid = (20 c-groups, B). Each block: one b, 25 c's.
// Middle 9 tokens (g_mid[b]) staged once in smem; per-c only prefix/suffix
// come from L2. Streaming stores for the 360 MB write-once output.
// Blocks with cg==0 also emit the unknown row for their b.
// ---------------------------------------------------------------------------
__global__ void k_fill(const float4* __restrict__ pre,
                       const float4* __restrict__ suf,
                       const float4* __restrict__ upre,
                       const float4* __restrict__ usuf,
                       const float4* __restrict__ ust,
                       float4* __restrict__ out_known,
                       float4* __restrict__ out_unk) {
    __shared__ float4 mid[MID_F4];        // 18 KB
    int cg = blockIdx.x, b = blockIdx.y;
    int tid = threadIdx.x;
    const float4* gm = ((const float4*)g_mid) + (size_t)b * MID_F4;
    for (int i = tid; i < MID_F4; i += 512) mid[i] = gm[i];
    __syncthreads();

    int c0 = cg * 25;
    for (int c = c0; c < c0 + 25; c++) {
        const float4* pr = pre + (size_t)c * D4;
        const float4* su = suf + (size_t)c * D4;
        float4* o = out_known + ((size_t)b * C + c) * (TOK_K * D4);
        for (int i = tid; i < TOK_K * D4; i += 512) {
            float4 v;
            if (i < 128)        v = __ldg(&pr[i]);
            else if (i < 1280)  v = mid[i - 128];
            else                v = __ldg(&su[i - 1280]);
            __stcs(&o[i], v);
        }
    }

    if (cg == 0) {
        float4* o = out_unk + (size_t)b * (TOK_U * D4);
        for (int i = tid; i < TOK_U * D4; i += 512) {
            int t = i >> 7, d4 = i & (D4 - 1);
            float4 v;
            if (t == 0)      v = __ldg(&upre[d4]);
            else if (t == 1) v = mid[d4];
            else if (t == 6) v = __ldg(&usuf[d4]);
            else             v = __ldg(&ust[(size_t)(t - 2) * D4 + d4]);
            __stcs(&o[i], v);
        }
    }
}

extern "C" void kernel_launch(void* const* d_in, const int* in_sizes, int n_in,
                              void* d_out, int out_size) {
    const float* patch = (const float*)d_in[0];   // (B,P,D)
    const float* gfeat = (const float*)d_in[1];   // (B,D)
    const float* query = (const float*)d_in[2];   // (H,D)
    const float* domW  = (const float*)d_in[3];   // (D,D)
    const float* domb  = (const float*)d_in[4];   // (D,)
    const float* semW  = (const float*)d_in[5];   // (H,D,D)
    const float* semb  = (const float*)d_in[6];   // (H,D)
    const float* ust   = (const float*)d_in[7];   // (U,D)
    const float* kpre  = (const float*)d_in[8];   // (C,1,D)
    const float* ksuf  = (const float*)d_in[9];   // (C,1,D)
    const float* upre  = (const float*)d_in[10];  // (1,D)
    const float* usuf  = (const float*)d_in[11];  // (1,D)

    float* out = (float*)d_out;
    float* out_known = out;
    float* out_unk   = out + OUT_UNK;
    float* out_sem   = out + OUT_SEM;

    k_scores<<<B * P, 256>>>((const float4*)patch, (const float4*)query);
    k_dom<<<B, 512>>>(gfeat, domW, domb);
    k_tokens<<<dim3(B, 4), 128>>>(patch, out_sem);
    k_sem<<<dim3(32, H), 256>>>(out_sem, (const float4*)semW, semb);
    k_fill<<<dim3(20, B), 512>>>((const float4*)kpre, (const float4*)ksuf,
                                 (const float4*)upre, (const float4*)usuf,
                                 (const float4*)ust,
                                 (float4*)out_known, (float4*)out_unk);
}

// round 4
// speedup vs baseline: 1.2036x; 1.2036x over previous
#include <cuda_runtime.h>
#include <cuda_bf16.h>
#include <cstdint>

// Problem constants
#define B 32
#define P 196
#define D 512
#define H 8
#define U 4
#define C 500

#define D4 128            // D / 4 (float4)
#define TOK_K 11
#define TOK_U 7

#define N_KNOWN   (16000LL * TOK_K * D)
#define OUT_UNK   (N_KNOWN)
#define N_UNK     ((long long)B * TOK_U * D)
#define OUT_SEM   (OUT_UNK + N_UNK)

// Scratch
__device__ float g_scores[B * P * H];
// g_mid[b] = [dom (512) | psem h=0..7 (8*512)] = middle 9 tokens, contiguous
__device__ float g_mid[B * 9 * D];
#define MID_F4 (9 * D4)   // 1152

// ---------------------------------------------------------------------------
// K1: scores[b][p][h]
// ---------------------------------------------------------------------------
__global__ void k_scores(const float4* __restrict__ patch,
                         const float4* __restrict__ query) {
    int bp = blockIdx.x;
    int w = threadIdx.x >> 5, lane = threadIdx.x & 31;
    const float4* row = patch + (size_t)bp * D4;
    const float4* q = query + (size_t)w * D4;
    float acc = 0.f;
    #pragma unroll
    for (int k = 0; k < 4; k++) {
        float4 r = row[lane + 32 * k];
        float4 qq = q[lane + 32 * k];
        acc = fmaf(r.x, qq.x, acc);
        acc = fmaf(r.y, qq.y, acc);
        acc = fmaf(r.z, qq.z, acc);
        acc = fmaf(r.w, qq.w, acc);
    }
    #pragma unroll
    for (int o = 16; o; o >>= 1) acc += __shfl_xor_sync(0xffffffffu, acc, o);
    if (lane == 0) g_scores[(size_t)bp * H + w] = acc;
}

// ---------------------------------------------------------------------------
// K2: softmax + semantic tokens. grid=(B,4), block=128
// ---------------------------------------------------------------------------
__global__ void k_tokens(const float* __restrict__ patch,
                         float* __restrict__ out_sem) {
    __shared__ float sw[P][H + 1];
    int b = blockIdx.x, dc = blockIdx.y;
    int tid = threadIdx.x;
    for (int i = tid; i < P * H; i += 128) {
        int p = i >> 3, h = i & 7;
        sw[p][h] = g_scores[(size_t)b * P * H + i];
    }
    __syncthreads();

    int w = tid >> 5, lane = tid & 31;
    for (int h = w; h < H; h += 4) {
        float mx = -3.4e38f;
        for (int p = lane; p < P; p += 32) mx = fmaxf(mx, sw[p][h]);
        #pragma unroll
        for (int o = 16; o; o >>= 1) mx = fmaxf(mx, __shfl_xor_sync(0xffffffffu, mx, o));
        float sum = 0.f;
        for (int p = lane; p < P; p += 32) {
            float e = expf(sw[p][h] - mx);
            sw[p][h] = e;
            sum += e;
        }
        #pragma unroll
        for (int o = 16; o; o >>= 1) sum += __shfl_xor_sync(0xffffffffu, sum, o);
        float inv = 1.f / sum;
        for (int p = lane; p < P; p += 32) sw[p][h] *= inv;
    }
    __syncthreads();

    int d = dc * 128 + tid;
    float acc[H];
    #pragma unroll
    for (int h = 0; h < H; h++) acc[h] = 0.f;
    const float* pb = patch + (size_t)b * P * D + d;
    #pragma unroll 4
    for (int p = 0; p < P; p++) {
        float x = pb[(size_t)p * D];
        #pragma unroll
        for (int h = 0; h < H; h++) acc[h] = fmaf(sw[p][h], x, acc[h]);
    }
    #pragma unroll
    for (int h = 0; h < H; h++)
        out_sem[((size_t)b * H + h) * D + d] = acc[h];
}

// ---------------------------------------------------------------------------
// K3: projected_domain -> g_mid[b][0:512]
// ---------------------------------------------------------------------------
__global__ void k_dom(const float* __restrict__ G,
                      const float* __restrict__ W,
                      const float* __restrict__ bias) {
    __shared__ float gs[D];
    int b = blockIdx.x, tid = threadIdx.x;
    gs[tid] = G[(size_t)b * D + tid];
    __syncthreads();
    int w = tid >> 5, lane = tid & 31;
    for (int g = 0; g < 8; g++) {
        int e = w * 32 + g * 4;
        float a0 = 0.f, a1 = 0.f, a2 = 0.f, a3 = 0.f;
        const float* w0 = W + (size_t)(e + 0) * D;
        const float* w1 = W + (size_t)(e + 1) * D;
        const float* w2 = W + (size_t)(e + 2) * D;
        const float* w3 = W + (size_t)(e + 3) * D;
        #pragma unroll 4
        for (int d = lane; d < D; d += 32) {
            float x = gs[d];
            a0 = fmaf(w0[d], x, a0);
            a1 = fmaf(w1[d], x, a1);
            a2 = fmaf(w2[d], x, a2);
            a3 = fmaf(w3[d], x, a3);
        }
        #pragma unroll
        for (int o = 16; o; o >>= 1) {
            a0 += __shfl_xor_sync(0xffffffffu, a0, o);
            a1 += __shfl_xor_sync(0xffffffffu, a1, o);
            a2 += __shfl_xor_sync(0xffffffffu, a2, o);
            a3 += __shfl_xor_sync(0xffffffffu, a3, o);
        }
        if (lane == 0) {
            g_mid[(size_t)b * (9 * D) + e + 0] = a0 + bias[e + 0];
            g_mid[(size_t)b * (9 * D) + e + 1] = a1 + bias[e + 1];
            g_mid[(size_t)b * (9 * D) + e + 2] = a2 + bias[e + 2];
            g_mid[(size_t)b * (9 * D) + e + 3] = a3 + bias[e + 3];
        }
    }
}

// ---------------------------------------------------------------------------
// K4: projected_sem -> g_mid[b][(1+h)*512 + e]
// R2 structure, but each warp owns TWO e's: every LDS feeds 2 FMAs, half the
// shuffles per output. grid=(32 e-tiles of 16, H, 2 b-groups), block=256.
// ---------------------------------------------------------------------------
__global__ void k_sem(const float* __restrict__ S,
                      const float* __restrict__ W,
                      const float* __restrict__ bias) {
    __shared__ float ss[16][D];           // 32 KB
    int ec = blockIdx.x, h = blockIdx.y, b0 = blockIdx.z * 16;
    int tid = threadIdx.x, w = tid >> 5, lane = tid & 31;

    // stage 16 b-rows of S for this h (float4 coalesced)
    {
        const float4* S4 = (const float4*)S;
        float4* ss4 = (float4*)ss;
        for (int i = tid; i < 16 * D4; i += 256) {
            int bi = i >> 7, d4 = i & (D4 - 1);
            ss4[(size_t)bi * D4 + d4] = S4[(((size_t)(b0 + bi)) * H + h) * D4 + d4];
        }
    }
    __syncthreads();

    int e0 = ec * 16 + w * 2;             // warp's two e's
    const float* wr0 = W + ((size_t)h * D + e0 + 0) * D;
    const float* wr1 = W + ((size_t)h * D + e0 + 1) * D;
    float wa[16], wb[16];
    #pragma unroll
    for (int k = 0; k < 16; k++) {
        wa[k] = wr0[lane + 32 * k];
        wb[k] = wr1[lane + 32 * k];
    }
    float bv0 = bias[(size_t)h * D + e0 + 0];
    float bv1 = bias[(size_t)h * D + e0 + 1];

    for (int bg = 0; bg < 16; bg += 4) {
        float a00 = 0.f, a01 = 0.f, a02 = 0.f, a03 = 0.f;
        float a10 = 0.f, a11 = 0.f, a12 = 0.f, a13 = 0.f;
        #pragma unroll
        for (int k = 0; k < 16; k++) {
            int idx = lane + 32 * k;
            float s0 = ss[bg + 0][idx];
            float s1 = ss[bg + 1][idx];
            float s2 = ss[bg + 2][idx];
            float s3 = ss[bg + 3][idx];
            a00 = fmaf(wa[k], s0, a00);
            a01 = fmaf(wa[k], s1, a01);
            a02 = fmaf(wa[k], s2, a02);
            a03 = fmaf(wa[k], s3, a03);
            a10 = fmaf(wb[k], s0, a10);
            a11 = fmaf(wb[k], s1, a11);
            a12 = fmaf(wb[k], s2, a12);
            a13 = fmaf(wb[k], s3, a13);
        }
        #pragma unroll
        for (int o = 16; o; o >>= 1) {
            a00 += __shfl_xor_sync(0xffffffffu, a00, o);
            a01 += __shfl_xor_sync(0xffffffffu, a01, o);
            a02 += __shfl_xor_sync(0xffffffffu, a02, o);
            a03 += __shfl_xor_sync(0xffffffffu, a03, o);
            a10 += __shfl_xor_sync(0xffffffffu, a10, o);
            a11 += __shfl_xor_sync(0xffffffffu, a11, o);
            a12 += __shfl_xor_sync(0xffffffffu, a12, o);
            a13 += __shfl_xor_sync(0xffffffffu, a13, o);
        }
        if (lane == 0) {
            size_t r0 = ((size_t)(b0 + bg + 0)) * (9 * D) + (size_t)(1 + h) * D;
            size_t r1 = ((size_t)(b0 + bg + 1)) * (9 * D) + (size_t)(1 + h) * D;
            size_t r2 = ((size_t)(b0 + bg + 2)) * (9 * D) + (size_t)(1 + h) * D;
            size_t r3 = ((size_t)(b0 + bg + 3)) * (9 * D) + (size_t)(1 + h) * D;
            g_mid[r0 + e0] = a00 + bv0;  g_mid[r0 + e0 + 1] = a10 + bv1;
            g_mid[r1 + e0] = a01 + bv0;  g_mid[r1 + e0 + 1] = a11 + bv1;
            g_mid[r2 + e0] = a02 + bv0;  g_mid[r2 + e0 + 1] = a12 + bv1;
            g_mid[r3 + e0] = a03 + bv0;  g_mid[r3 + e0 + 1] = a13 + bv1;
        }
    }
}

// ---------------------------------------------------------------------------
// K5: prompt fill. ONE BLOCK PER ROW (R2 assignment: concurrent blocks write
// adjacent rows) + smem-staged mid tokens (cuts 288 MB of repeated L2 reads).
// Blocks [0,16000): known row bc.  Blocks [16000,16032): unknown row b.
// ---------------------------------------------------------------------------
__global__ void k_fill(const float4* __restrict__ pre,
                       const float4* __restrict__ suf,
                       const float4* __restrict__ upre,
                       const float4* __restrict__ usuf,
                       const float4* __restrict__ ust,
                       float4* __restrict__ out_known,
                       float4* __restrict__ out_unk) {
    __shared__ float4 mid[MID_F4];        // 18 KB
    int bc = blockIdx.x;
    int tid = threadIdx.x;
    if (bc < 16000) {
        int b = bc / C, c = bc - b * C;
        const float4* gm = ((const float4*)g_mid) + (size_t)b * MID_F4;
        for (int i = tid; i < MID_F4; i += 512) mid[i] = __ldg(&gm[i]);
        __syncthreads();

        const float4* pr = pre + (size_t)c * D4;
        const float4* su = suf + (size_t)c * D4;
        float4* o = out_known + (size_t)bc * (TOK_K * D4);
        for (int i = tid; i < TOK_K * D4; i += 512) {
            float4 v;
            if (i < 128)        v = __ldg(&pr[i]);
            else if (i < 1280)  v = mid[i - 128];
            else                v = __ldg(&su[i - 1280]);
            __stcs(&o[i], v);
        }
    } else {
        int b = bc - 16000;
        const float4* gm = ((const float4*)g_mid) + (size_t)b * MID_F4;
        float4* o = out_unk + (size_t)b * (TOK_U * D4);
        for (int i = tid; i < TOK_U * D4; i += 512) {
            int t = i >> 7, d4 = i & (D4 - 1);
            float4 v;
            if (t == 0)      v = __ldg(&upre[d4]);
            else if (t == 1) v = __ldg(&gm[d4]);
            else if (t == 6) v = __ldg(&usuf[d4]);
            else             v = __ldg(&ust[(size_t)(t - 2) * D4 + d4]);
            __stcs(&o[i], v);
        }
    }
}

extern "C" void kernel_launch(void* const* d_in, const int* in_sizes, int n_in,
                              void* d_out, int out_size) {
    const float* patch = (const float*)d_in[0];
    const float* gfeat = (const float*)d_in[1];
    const float* query = (const float*)d_in[2];
    const float* domW  = (const float*)d_in[3];
    const float* domb  = (const float*)d_in[4];
    const float* semW  = (const float*)d_in[5];
    const float* semb  = (const float*)d_in[6];
    const float* ust   = (const float*)d_in[7];
    const float* kpre  = (const float*)d_in[8];
    const float* ksuf  = (const float*)d_in[9];
    const float* upre  = (const float*)d_in[10];
    const float* usuf  = (const float*)d_in[11];

    float* out = (float*)d_out;
    float* out_known = out;
    float* out_unk   = out + OUT_UNK;
    float* out_sem   = out + OUT_SEM;

    k_scores<<<B * P, 256>>>((const float4*)patch, (const float4*)query);
    k_dom<<<B, 512>>>(gfeat, domW, domb);
    k_tokens<<<dim3(B, 4), 128>>>(patch, out_sem);
    k_sem<<<dim3(32, H, 2), 256>>>(out_sem, semW, semb);
    k_fill<<<16032, 512>>>((const float4*)kpre, (const float4*)ksuf,
                           (const float4*)upre, (const float4*)usuf,
                           (const float4*)ust,
                           (float4*)out_known, (float4*)out_unk);
}